// round 5
// baseline (speedup 1.0000x reference)
#include <cuda_runtime.h>
#include <cuda_bf16.h>
#include <math.h>
#include <stdint.h>

#define BB 2
#define SS 2048
#define DD 1024
#define HH 16
#define DH 64
#define BH (BB*HH)          // 32
#define MROWS (BB*SS)       // 4096

// Scratch (device globals: allocation-free)
__device__ float g_Q[BH * SS * DH];
__device__ float g_K[BH * SS * DH];
__device__ float g_V[BH * SS * DH];
__device__ float g_Ctx[MROWS * DD];

__device__ __forceinline__ uint32_t cvt_u(float x) {
    uint32_t u;
    asm("cvt.rna.tf32.f32 %0, %1;" : "=r"(u) : "f"(x));
    return u;
}

#define MMA_TF32(c, a, b)                                                     \
    asm volatile(                                                             \
        "mma.sync.aligned.m16n8k8.row.col.f32.tf32.tf32.f32 "                 \
        "{%0,%1,%2,%3},{%4,%5,%6,%7},{%8,%9},{%0,%1,%2,%3};\n"                \
        : "+f"(c[0]), "+f"(c[1]), "+f"(c[2]), "+f"(c[3])                      \
        : "r"(a[0]), "r"(a[1]), "r"(a[2]), "r"(a[3]), "r"(b[0]), "r"(b[1]))

#define CP16(dst_u32, src_ptr)                                                \
    asm volatile("cp.async.ca.shared.global [%0], [%1], 16;\n"                \
                 :: "r"(dst_u32), "l"(src_ptr))

__device__ __forceinline__ void sm_merge(float& m, float& s, float om, float os) {
    float M = fmaxf(m, om);
    float e1 = (m  > -INFINITY) ? __expf(m  - M) : 0.0f;
    float e2 = (om > -INFINITY) ? __expf(om - M) : 0.0f;
    s = s * e1 + os * e2;
    m = M;
}

// ---------------------------------------------------------------------------
// TF32 MMA GEMM with cp.async 2-stage pipeline: C = A*B^T + bias.
// A[M,1024] rm, B[N,1024] rm. BM=BN=128, BK=32, 256 thr, warp tile 64x32.
// MODE 0: proj (scatter to [B,H,S,DH]) | MODE 1: dense (row-major)
// ---------------------------------------------------------------------------
template<int MODE>
__global__ __launch_bounds__(256, 2)
void mma_nt(const float* __restrict__ A, const float* __restrict__ Bw,
            const float* __restrict__ bias, float* __restrict__ C)
{
    extern __shared__ float sm[];
    float* pA = sm;               // 2 stages x 128x36
    float* pB = sm + 2 * 4608;

    const int tid = threadIdx.x;
    const int wid = tid >> 5, lane = tid & 31;
    const int g = lane >> 2, q = lane & 3;
    const int wm0 = (wid >> 2) * 64;
    const int wn0 = (wid & 3) * 32;
    const int row0 = blockIdx.y * 128;
    const int col0 = blockIdx.x * 128;
    const int K = DD;

    uint32_t sA = (uint32_t)__cvta_generic_to_shared(pA);
    uint32_t sB = (uint32_t)__cvta_generic_to_shared(pB);

    float acc[4][4][4];
    #pragma unroll
    for (int i = 0; i < 4; ++i)
        #pragma unroll
        for (int j = 0; j < 4; ++j)
            #pragma unroll
            for (int r = 0; r < 4; ++r) acc[i][j][r] = 0.0f;

    auto copy_tile = [&](int st, int kt) {
        #pragma unroll
        for (int it = 0; it < 4; ++it) {
            const int idx = tid + it * 256;
            const int r = idx >> 3, c4 = (idx & 7) << 2;
            CP16(sA + (uint32_t)(st * 4608 + r * 36 + c4) * 4,
                 &A[(size_t)(row0 + r) * K + kt + c4]);
            CP16(sB + (uint32_t)(st * 4608 + r * 36 + c4) * 4,
                 &Bw[(size_t)(col0 + r) * K + kt + c4]);
        }
        asm volatile("cp.async.commit_group;\n");
    };

    copy_tile(0, 0);
    const int T = K / 32;
    for (int t = 0; t < T; ++t) {
        if (t + 1 < T) {
            copy_tile((t + 1) & 1, (t + 1) * 32);
            asm volatile("cp.async.wait_group 1;\n");
        } else {
            asm volatile("cp.async.wait_group 0;\n");
        }
        __syncthreads();
        const float* Asb = pA + (t & 1) * 4608;
        const float* Bsb = pB + (t & 1) * 4608;
        #pragma unroll
        for (int kk = 0; kk < 4; ++kk) {
            const int kb = kk * 8;
            uint32_t a[4][4], b[4][2];
            #pragma unroll
            for (int i = 0; i < 4; ++i) {
                a[i][0] = cvt_u(Asb[(wm0 + 16*i + g    ) * 36 + kb + q    ]);
                a[i][1] = cvt_u(Asb[(wm0 + 16*i + g + 8) * 36 + kb + q    ]);
                a[i][2] = cvt_u(Asb[(wm0 + 16*i + g    ) * 36 + kb + q + 4]);
                a[i][3] = cvt_u(Asb[(wm0 + 16*i + g + 8) * 36 + kb + q + 4]);
            }
            #pragma unroll
            for (int j = 0; j < 4; ++j) {
                b[j][0] = cvt_u(Bsb[(wn0 + 8*j + g) * 36 + kb + q    ]);
                b[j][1] = cvt_u(Bsb[(wn0 + 8*j + g) * 36 + kb + q + 4]);
            }
            #pragma unroll
            for (int i = 0; i < 4; ++i)
                #pragma unroll
                for (int j = 0; j < 4; ++j)
                    MMA_TF32(acc[i][j], a[i], b[j]);
        }
        __syncthreads();
    }

    #pragma unroll
    for (int i = 0; i < 4; ++i) {
        #pragma unroll
        for (int rr = 0; rr < 2; ++rr) {
            const int gr = row0 + wm0 + 16*i + g + rr*8;
            #pragma unroll
            for (int j = 0; j < 4; ++j) {
                const int gc = col0 + wn0 + 8*j + 2*q;
                const float v0 = acc[i][j][rr*2 + 0];
                const float v1 = acc[i][j][rr*2 + 1];
                float2 bv = *(const float2*)&bias[gc];
                if (MODE == 0) {
                    const int b = gr >> 11, s = gr & 2047;
                    const int h = gc >> 6, d = gc & 63;
                    *(float2*)&C[(((size_t)(b*HH + h))*SS + s)*DH + d] =
                        make_float2(v0 + bv.x, v1 + bv.y);
                } else {
                    *(float2*)&C[(size_t)gr * DD + gc] =
                        make_float2(v0 + bv.x, v1 + bv.y);
                }
            }
        }
    }
}

// ---------------------------------------------------------------------------
// Fused attention, 512 threads (16 warps), 128-row blocks.
// Pass 1: online (max, expsum) stats over recomputed score tiles.
// Pass 2: recompute scores, normalize, stage full 128x128 w tile in smem,
//         write weights coalesced from smem, AV MMA from staged tile.
// Scores warp layout (4x4): wm0=(wid>>2)*32, wn0=(wid&3)*32, tile 32x32.
// AV warp layout (4x4):     wm0, wn0a=(wid&3)*16, tile 32x16.
// smem (floats): sQ 8704 | sK 8704 | sV 8704 | sW 16896 | red 1024 | M/I 256
// ---------------------------------------------------------------------------
#define SQ_OFF 0
#define SK_OFF 8704
#define SV_OFF 17408
#define SW_OFF 26112
#define RM_OFF 43008
#define RS_OFF 43520
#define SMO    44032
#define SIO    44160
#define SM_ATTN_FLOATS 44288

__global__ __launch_bounds__(512, 1)
void attn_fused(const float* __restrict__ Q, const float* __restrict__ Kh,
                const float* __restrict__ Vh, const int* __restrict__ maskAll,
                float* __restrict__ Wts, float* __restrict__ Ctx)
{
    extern __shared__ float sm[];
    float* sQ = sm + SQ_OFF;     // [128][68] raw fp32
    float* sK = sm + SK_OFF;     // [128][68] raw fp32 (rows = key index)
    float* sV = sm + SV_OFF;     // [128][68] raw fp32 (rows = key index, cols = dh)
    float* sW = sm + SW_OFF;     // [128][132] fp32 normalized weights tile
    float* red_m = sm + RM_OFF;  // [128][4]
    float* red_s = sm + RS_OFF;  // [128][4]
    float* sM = sm + SMO;        // [128]
    float* sI = sm + SIO;        // [128]

    const int tid = threadIdx.x;
    const int wid = tid >> 5, lane = tid & 31;
    const int g = lane >> 2, q = lane & 3;
    const int wr = wid >> 2, wc = wid & 3;
    const int wm0 = wr * 32;       // scores + AV row base
    const int wn0 = wc * 32;       // scores col base
    const int wn0a = wc * 16;      // AV col base

    const int z = blockIdx.y;
    const int row0 = blockIdx.x * 128;

    const float* Qz = Q  + (size_t)z * SS * DH;
    const float* Kz = Kh + (size_t)z * SS * DH;
    const float* Vz = Vh + (size_t)z * SS * DH;
    float* Wz = Wts + (size_t)z * SS * SS;
    const int* mask = maskAll + (size_t)(z / HH) * SS * SS;

    // Load Q tile once (raw fp32)
    #pragma unroll
    for (int it = 0; it < 4; ++it) {
        const int idx = tid + it * 512;
        const int r = idx >> 4, c4 = (idx & 15) << 2;
        *(float4*)&sQ[r * 68 + c4] = *(const float4*)&Qz[(size_t)(row0 + r) * DH + c4];
    }

    // ---------------- PASS 1: stats ----------------
    float m4[2][2], s4[2][2];
    #pragma unroll
    for (int i = 0; i < 2; ++i)
        #pragma unroll
        for (int rr = 0; rr < 2; ++rr) { m4[i][rr] = -INFINITY; s4[i][rr] = 0.0f; }

    for (int ct = 0; ct < SS / 128; ++ct) {
        #pragma unroll
        for (int it = 0; it < 4; ++it) {
            const int idx = tid + it * 512;
            const int r = idx >> 4, c4 = (idx & 15) << 2;
            *(float4*)&sK[r * 68 + c4] =
                *(const float4*)&Kz[(size_t)(ct * 128 + r) * DH + c4];
        }
        __syncthreads();

        float acc[2][4][4];
        #pragma unroll
        for (int i = 0; i < 2; ++i)
            #pragma unroll
            for (int j = 0; j < 4; ++j)
                #pragma unroll
                for (int r = 0; r < 4; ++r) acc[i][j][r] = 0.0f;

        #pragma unroll
        for (int kk = 0; kk < 8; ++kk) {
            const int kb = kk * 8;
            uint32_t a[2][4], b[4][2];
            #pragma unroll
            for (int i = 0; i < 2; ++i) {
                a[i][0] = cvt_u(sQ[(wm0 + 16*i + g    ) * 68 + kb + q    ]);
                a[i][1] = cvt_u(sQ[(wm0 + 16*i + g + 8) * 68 + kb + q    ]);
                a[i][2] = cvt_u(sQ[(wm0 + 16*i + g    ) * 68 + kb + q + 4]);
                a[i][3] = cvt_u(sQ[(wm0 + 16*i + g + 8) * 68 + kb + q + 4]);
            }
            #pragma unroll
            for (int j = 0; j < 4; ++j) {
                b[j][0] = cvt_u(sK[(wn0 + 8*j + g) * 68 + kb + q    ]);
                b[j][1] = cvt_u(sK[(wn0 + 8*j + g) * 68 + kb + q + 4]);
            }
            #pragma unroll
            for (int i = 0; i < 2; ++i)
                #pragma unroll
                for (int j = 0; j < 4; ++j)
                    MMA_TF32(acc[i][j], a[i], b[j]);
        }

        #pragma unroll
        for (int i = 0; i < 2; ++i) {
            #pragma unroll
            for (int rr = 0; rr < 2; ++rr) {
                const int gr = row0 + wm0 + 16*i + g + rr*8;
                float vals[8];
                float mt = -INFINITY;
                #pragma unroll
                for (int j = 0; j < 4; ++j) {
                    const int gc = ct * 128 + wn0 + 8*j + 2*q;
                    int2 mv = *(const int2*)&mask[(size_t)gr * SS + gc];
                    float v0 = mv.x ? acc[i][j][rr*2 + 0] * 0.125f : -INFINITY;
                    float v1 = mv.y ? acc[i][j][rr*2 + 1] * 0.125f : -INFINITY;
                    vals[j*2] = v0; vals[j*2+1] = v1;
                    mt = fmaxf(mt, fmaxf(v0, v1));
                }
                const float Mn = fmaxf(m4[i][rr], mt);
                if (Mn > -INFINITY) {
                    float add = 0.0f;
                    #pragma unroll
                    for (int e = 0; e < 8; ++e)
                        add += (vals[e] > -INFINITY) ? __expf(vals[e] - Mn) : 0.0f;
                    const float keep = (m4[i][rr] > -INFINITY)
                                     ? s4[i][rr] * __expf(m4[i][rr] - Mn) : 0.0f;
                    s4[i][rr] = keep + add;
                    m4[i][rr] = Mn;
                }
            }
        }
        __syncthreads();
    }

    // reduce: across q lanes, then across 4 col-warps
    #pragma unroll
    for (int i = 0; i < 2; ++i) {
        #pragma unroll
        for (int rr = 0; rr < 2; ++rr) {
            float m = m4[i][rr], s = s4[i][rr];
            #pragma unroll
            for (int o = 1; o <= 2; o <<= 1) {
                float om = __shfl_xor_sync(0xffffffffu, m, o);
                float os = __shfl_xor_sync(0xffffffffu, s, o);
                sm_merge(m, s, om, os);
            }
            if (q == 0) {
                const int R = wm0 + 16*i + g + rr*8;
                red_m[R * 4 + wc] = m;
                red_s[R * 4 + wc] = s;
            }
        }
    }
    __syncthreads();
    if (tid < 128) {
        float m = red_m[tid * 4], s = red_s[tid * 4];
        #pragma unroll
        for (int w = 1; w < 4; ++w)
            sm_merge(m, s, red_m[tid * 4 + w], red_s[tid * 4 + w]);
        sM[tid] = m;
        sI[tid] = (s > 0.0f) ? 1.0f / s : 0.0f;
    }
    __syncthreads();

    // ---------------- PASS 2: weights + AV ----------------
    float acc_av[2][2][4];
    #pragma unroll
    for (int i = 0; i < 2; ++i)
        #pragma unroll
        for (int j = 0; j < 2; ++j)
            #pragma unroll
            for (int r = 0; r < 4; ++r) acc_av[i][j][r] = 0.0f;

    for (int ct = 0; ct < SS / 128; ++ct) {
        #pragma unroll
        for (int it = 0; it < 4; ++it) {
            const int idx = tid + it * 512;
            const int r = idx >> 4, c4 = (idx & 15) << 2;
            *(float4*)&sK[r * 68 + c4] =
                *(const float4*)&Kz[(size_t)(ct * 128 + r) * DH + c4];
            *(float4*)&sV[r * 68 + c4] =
                *(const float4*)&Vz[(size_t)(ct * 128 + r) * DH + c4];
        }
        __syncthreads();

        // recompute score tile
        float acc[2][4][4];
        #pragma unroll
        for (int i = 0; i < 2; ++i)
            #pragma unroll
            for (int j = 0; j < 4; ++j)
                #pragma unroll
                for (int r = 0; r < 4; ++r) acc[i][j][r] = 0.0f;

        #pragma unroll
        for (int kk = 0; kk < 8; ++kk) {
            const int kb = kk * 8;
            uint32_t a[2][4], b[4][2];
            #pragma unroll
            for (int i = 0; i < 2; ++i) {
                a[i][0] = cvt_u(sQ[(wm0 + 16*i + g    ) * 68 + kb + q    ]);
                a[i][1] = cvt_u(sQ[(wm0 + 16*i + g + 8) * 68 + kb + q    ]);
                a[i][2] = cvt_u(sQ[(wm0 + 16*i + g    ) * 68 + kb + q + 4]);
                a[i][3] = cvt_u(sQ[(wm0 + 16*i + g + 8) * 68 + kb + q + 4]);
            }
            #pragma unroll
            for (int j = 0; j < 4; ++j) {
                b[j][0] = cvt_u(sK[(wn0 + 8*j + g) * 68 + kb + q    ]);
                b[j][1] = cvt_u(sK[(wn0 + 8*j + g) * 68 + kb + q + 4]);
            }
            #pragma unroll
            for (int i = 0; i < 2; ++i)
                #pragma unroll
                for (int j = 0; j < 4; ++j)
                    MMA_TF32(acc[i][j], a[i], b[j]);
        }

        // normalize -> stage full w tile in sW (fp32)
        #pragma unroll
        for (int i = 0; i < 2; ++i) {
            #pragma unroll
            for (int rr = 0; rr < 2; ++rr) {
                const int R  = wm0 + 16*i + g + rr*8;
                const int gr = row0 + R;
                const float M = sM[R], I = sI[R];
                #pragma unroll
                for (int j = 0; j < 4; ++j) {
                    const int c = wn0 + 8*j + 2*q;
                    int2 mv = *(const int2*)&mask[(size_t)gr * SS + ct * 128 + c];
                    float w0 = mv.x ? __expf(acc[i][j][rr*2    ] * 0.125f - M) * I : 0.0f;
                    float w1 = mv.y ? __expf(acc[i][j][rr*2 + 1] * 0.125f - M) * I : 0.0f;
                    *(float2*)&sW[R * 132 + c] = make_float2(w0, w1);
                }
            }
        }
        __syncthreads();

        // coalesced weights write from sW
        #pragma unroll
        for (int it = 0; it < 8; ++it) {
            const int idx = tid + it * 512;
            const int r = idx >> 5, c4 = (idx & 31) << 2;
            *(float4*)&Wz[(size_t)(row0 + r) * SS + ct * 128 + c4] =
                *(const float4*)&sW[r * 132 + c4];
        }

        // AV MMA over k=128 from staged tile
        #pragma unroll
        for (int kk = 0; kk < 16; ++kk) {
            const int kb = kk * 8;
            uint32_t a[2][4], b[2][2];
            #pragma unroll
            for (int i = 0; i < 2; ++i) {
                a[i][0] = cvt_u(sW[(wm0 + 16*i + g    ) * 132 + kb + q    ]);
                a[i][1] = cvt_u(sW[(wm0 + 16*i + g + 8) * 132 + kb + q    ]);
                a[i][2] = cvt_u(sW[(wm0 + 16*i + g    ) * 132 + kb + q + 4]);
                a[i][3] = cvt_u(sW[(wm0 + 16*i + g + 8) * 132 + kb + q + 4]);
            }
            #pragma unroll
            for (int j = 0; j < 2; ++j) {
                b[j][0] = cvt_u(sV[(kb + q    ) * 68 + wn0a + 8*j + g]);
                b[j][1] = cvt_u(sV[(kb + q + 4) * 68 + wn0a + 8*j + g]);
            }
            #pragma unroll
            for (int i = 0; i < 2; ++i)
                #pragma unroll
                for (int j = 0; j < 2; ++j)
                    MMA_TF32(acc_av[i][j], a[i], b[j]);
        }
        __syncthreads();
    }

    // write ctx (merged heads)
    const int b = z / HH, h = z % HH;
    #pragma unroll
    for (int i = 0; i < 2; ++i) {
        #pragma unroll
        for (int rr = 0; rr < 2; ++rr) {
            const int s = row0 + wm0 + 16*i + g + rr*8;
            #pragma unroll
            for (int j = 0; j < 2; ++j) {
                const int n = wn0a + 8*j + 2*q;
                *(float2*)&Ctx[((size_t)(b*SS + s))*DD + h*64 + n] =
                    make_float2(acc_av[i][j][rr*2], acc_av[i][j][rr*2 + 1]);
            }
        }
    }
}

// ---------------------------------------------------------------------------
extern "C" void kernel_launch(void* const* d_in, const int* in_sizes, int n_in,
                              void* d_out, int out_size)
{
    const float* q       = (const float*)d_in[0];
    const float* k       = (const float*)d_in[1];
    const float* v       = (const float*)d_in[2];
    const int*   mask    = (const int*)d_in[3];
    const float* wq_w    = (const float*)d_in[4];
    const float* wq_b    = (const float*)d_in[5];
    const float* wk_w    = (const float*)d_in[6];
    const float* wk_b    = (const float*)d_in[7];
    const float* wv_w    = (const float*)d_in[8];
    const float* wv_b    = (const float*)d_in[9];
    const float* dense_w = (const float*)d_in[10];
    const float* dense_b = (const float*)d_in[11];

    float* out = (float*)d_out;
    float* wts = out + (size_t)BB * SS * DD;

    void *pQ, *pK, *pV, *pC;
    cudaGetSymbolAddress(&pQ, g_Q);
    cudaGetSymbolAddress(&pK, g_K);
    cudaGetSymbolAddress(&pV, g_V);
    cudaGetSymbolAddress(&pC, g_Ctx);
    float* gQ = (float*)pQ;
    float* gK = (float*)pK;
    float* gV = (float*)pV;
    float* gC = (float*)pC;

    const int SM_GEMM = 73728;
    const int SM_ATTN = SM_ATTN_FLOATS * 4;   // 177152 B
    static int inited = 0;
    if (!inited) {
        cudaFuncSetAttribute(mma_nt<0>, cudaFuncAttributeMaxDynamicSharedMemorySize, SM_GEMM);
        cudaFuncSetAttribute(mma_nt<1>, cudaFuncAttributeMaxDynamicSharedMemorySize, SM_GEMM);
        cudaFuncSetAttribute(attn_fused, cudaFuncAttributeMaxDynamicSharedMemorySize, SM_ATTN);
        inited = 1;
    }

    const dim3 gproj(DD / 128, MROWS / 128, 1);       // (8, 32)
    mma_nt<0><<<gproj, 256, SM_GEMM>>>(q, wq_w, wq_b, gQ);
    mma_nt<0><<<gproj, 256, SM_GEMM>>>(k, wk_w, wk_b, gK);
    mma_nt<0><<<gproj, 256, SM_GEMM>>>(v, wv_w, wv_b, gV);

    const dim3 gattn(SS / 128, BH, 1);                // (16, 32)
    attn_fused<<<gattn, 512, SM_ATTN>>>(gQ, gK, gV, mask, wts, gC);

    mma_nt<1><<<gproj, 256, SM_GEMM>>>(gC, dense_w, dense_b, out);
}

// round 6
// speedup vs baseline: 1.4405x; 1.4405x over previous
#include <cuda_runtime.h>
#include <cuda_bf16.h>
#include <math.h>
#include <stdint.h>

#define BB 2
#define SS 2048
#define DD 1024
#define HH 16
#define DH 64
#define BH (BB*HH)          // 32
#define MROWS (BB*SS)       // 4096
#define NROWTOT (BH*SS)     // 65536 score rows

// Scratch (device globals: allocation-free)
__device__ float  g_Q[BH * SS * DH];
__device__ float  g_K[BH * SS * DH];
__device__ float  g_V[BH * SS * DH];
__device__ float  g_Ctx[MROWS * DD];
__device__ float2 g_Part[(size_t)NROWTOT * 16];   // per-row per-colblock (max, expsum)
__device__ float2 g_Stats[NROWTOT];               // per-row (max, 1/sum)

__device__ __forceinline__ float to_tf32(float x) {
    uint32_t u;
    asm("cvt.rna.tf32.f32 %0, %1;" : "=r"(u) : "f"(x));
    return __uint_as_float(u);
}
__device__ __forceinline__ uint32_t cvt_u(float x) {
    uint32_t u;
    asm("cvt.rna.tf32.f32 %0, %1;" : "=r"(u) : "f"(x));
    return u;
}

#define MMA_TF32(c, a, b)                                                     \
    asm volatile(                                                             \
        "mma.sync.aligned.m16n8k8.row.col.f32.tf32.tf32.f32 "                 \
        "{%0,%1,%2,%3},{%4,%5,%6,%7},{%8,%9},{%0,%1,%2,%3};\n"                \
        : "+f"(c[0]), "+f"(c[1]), "+f"(c[2]), "+f"(c[3])                      \
        : "r"(a[0]), "r"(a[1]), "r"(a[2]), "r"(a[3]), "r"(b[0]), "r"(b[1]))

#define CP16(dst_u32, src_ptr)                                                \
    asm volatile("cp.async.ca.shared.global [%0], [%1], 16;\n"                \
                 :: "r"(dst_u32), "l"(src_ptr))

__device__ __forceinline__ void sm_merge(float& m, float& s, float om, float os) {
    float M = fmaxf(m, om);
    float e1 = (m  > -INFINITY) ? __expf(m  - M) : 0.0f;
    float e2 = (om > -INFINITY) ? __expf(om - M) : 0.0f;
    s = s * e1 + os * e2;
    m = M;
}

// ---------------------------------------------------------------------------
// TF32 MMA GEMM with cp.async 2-stage pipeline: C = A*B^T + bias.
// A[M,1024] rm, B[N,1024] rm. BM=BN=128, BK=32, 256 thr, warp tile 64x32.
// MODE 0: proj (scatter to [B,H,S,DH]) | MODE 1: dense (row-major)
// ---------------------------------------------------------------------------
template<int MODE>
__global__ __launch_bounds__(256, 2)
void mma_nt(const float* __restrict__ A, const float* __restrict__ Bw,
            const float* __restrict__ bias, float* __restrict__ C)
{
    extern __shared__ float sm[];
    float* pA = sm;               // 2 stages x 128x36
    float* pB = sm + 2 * 4608;

    const int tid = threadIdx.x;
    const int wid = tid >> 5, lane = tid & 31;
    const int g = lane >> 2, q = lane & 3;
    const int wm0 = (wid >> 2) * 64;
    const int wn0 = (wid & 3) * 32;
    const int row0 = blockIdx.y * 128;
    const int col0 = blockIdx.x * 128;
    const int K = DD;

    uint32_t sA = (uint32_t)__cvta_generic_to_shared(pA);
    uint32_t sB = (uint32_t)__cvta_generic_to_shared(pB);

    float acc[4][4][4];
    #pragma unroll
    for (int i = 0; i < 4; ++i)
        #pragma unroll
        for (int j = 0; j < 4; ++j)
            #pragma unroll
            for (int r = 0; r < 4; ++r) acc[i][j][r] = 0.0f;

    auto copy_tile = [&](int st, int kt) {
        #pragma unroll
        for (int it = 0; it < 4; ++it) {
            const int idx = tid + it * 256;
            const int r = idx >> 3, c4 = (idx & 7) << 2;
            CP16(sA + (uint32_t)(st * 4608 + r * 36 + c4) * 4,
                 &A[(size_t)(row0 + r) * K + kt + c4]);
            CP16(sB + (uint32_t)(st * 4608 + r * 36 + c4) * 4,
                 &Bw[(size_t)(col0 + r) * K + kt + c4]);
        }
        asm volatile("cp.async.commit_group;\n");
    };

    copy_tile(0, 0);
    const int T = K / 32;
    for (int t = 0; t < T; ++t) {
        if (t + 1 < T) {
            copy_tile((t + 1) & 1, (t + 1) * 32);
            asm volatile("cp.async.wait_group 1;\n");
        } else {
            asm volatile("cp.async.wait_group 0;\n");
        }
        __syncthreads();
        const float* Asb = pA + (t & 1) * 4608;
        const float* Bsb = pB + (t & 1) * 4608;
        #pragma unroll
        for (int kk = 0; kk < 4; ++kk) {
            const int kb = kk * 8;
            uint32_t a[4][4], b[4][2];
            #pragma unroll
            for (int i = 0; i < 4; ++i) {
                a[i][0] = cvt_u(Asb[(wm0 + 16*i + g    ) * 36 + kb + q    ]);
                a[i][1] = cvt_u(Asb[(wm0 + 16*i + g + 8) * 36 + kb + q    ]);
                a[i][2] = cvt_u(Asb[(wm0 + 16*i + g    ) * 36 + kb + q + 4]);
                a[i][3] = cvt_u(Asb[(wm0 + 16*i + g + 8) * 36 + kb + q + 4]);
            }
            #pragma unroll
            for (int j = 0; j < 4; ++j) {
                b[j][0] = cvt_u(Bsb[(wn0 + 8*j + g) * 36 + kb + q    ]);
                b[j][1] = cvt_u(Bsb[(wn0 + 8*j + g) * 36 + kb + q + 4]);
            }
            #pragma unroll
            for (int i = 0; i < 4; ++i)
                #pragma unroll
                for (int j = 0; j < 4; ++j)
                    MMA_TF32(acc[i][j], a[i], b[j]);
        }
        __syncthreads();
    }

    #pragma unroll
    for (int i = 0; i < 4; ++i) {
        #pragma unroll
        for (int rr = 0; rr < 2; ++rr) {
            const int gr = row0 + wm0 + 16*i + g + rr*8;
            #pragma unroll
            for (int j = 0; j < 4; ++j) {
                const int gc = col0 + wn0 + 8*j + 2*q;
                const float v0 = acc[i][j][rr*2 + 0];
                const float v1 = acc[i][j][rr*2 + 1];
                float2 bv = *(const float2*)&bias[gc];
                if (MODE == 0) {
                    const int b = gr >> 11, s = gr & 2047;
                    const int h = gc >> 6, d = gc & 63;
                    *(float2*)&C[(((size_t)(b*HH + h))*SS + s)*DH + d] =
                        make_float2(v0 + bv.x, v1 + bv.y);
                } else {
                    *(float2*)&C[(size_t)gr * DD + gc] =
                        make_float2(v0 + bv.x, v1 + bv.y);
                }
            }
        }
    }
}

// ---------------------------------------------------------------------------
// Scores: per z: S = Q@K^T * 0.125, masked -> raw into weights region.
// Single BK=64 slab (K=DH). Epilogue also emits per-row (max, expsum)
// partials for its 128-col tile into g_Part.
// ---------------------------------------------------------------------------
__global__ __launch_bounds__(256, 2)
void scores_kernel(const float* __restrict__ Q, const float* __restrict__ Kh,
                   const int* __restrict__ maskAll, float* __restrict__ Wraw,
                   float2* __restrict__ Part)
{
    extern __shared__ float sm[];
    float* As = sm;            // 128 x 68
    float* Bs = sm + 8704;     // 128 x 68
    float* red_m = sm + 17408; // 128 x 4
    float* red_s = sm + 17920; // 128 x 4

    const int tid = threadIdx.x;
    const int wid = tid >> 5, lane = tid & 31;
    const int g = lane >> 2, q = lane & 3;
    const int wm0 = (wid >> 2) * 64;
    const int wn0 = (wid & 3) * 32;
    const int z = blockIdx.z;
    const int row0 = blockIdx.y * 128;
    const int col0 = blockIdx.x * 128;

    const float* Qz = Q  + (size_t)z * SS * DH;
    const float* Kz = Kh + (size_t)z * SS * DH;
    float* Cz = Wraw + (size_t)z * SS * SS;
    const int* mask = maskAll + (size_t)(z / HH) * SS * SS;

    #pragma unroll
    for (int it = 0; it < 8; ++it) {
        const int idx = tid + it * 256;
        const int r = idx >> 4, c4 = (idx & 15) << 2;
        float4 va = *(const float4*)&Qz[(size_t)(row0 + r) * DH + c4];
        *(float4*)&As[r * 68 + c4] = make_float4(to_tf32(va.x), to_tf32(va.y),
                                                 to_tf32(va.z), to_tf32(va.w));
        float4 vb = *(const float4*)&Kz[(size_t)(col0 + r) * DH + c4];
        *(float4*)&Bs[r * 68 + c4] = make_float4(to_tf32(vb.x), to_tf32(vb.y),
                                                 to_tf32(vb.z), to_tf32(vb.w));
    }
    __syncthreads();

    float acc[4][4][4];
    #pragma unroll
    for (int i = 0; i < 4; ++i)
        #pragma unroll
        for (int j = 0; j < 4; ++j)
            #pragma unroll
            for (int r = 0; r < 4; ++r) acc[i][j][r] = 0.0f;

    #pragma unroll
    for (int kk = 0; kk < 8; ++kk) {
        const int kb = kk * 8;
        uint32_t a[4][4], b[4][2];
        #pragma unroll
        for (int i = 0; i < 4; ++i) {
            a[i][0] = __float_as_uint(As[(wm0 + 16*i + g    ) * 68 + kb + q    ]);
            a[i][1] = __float_as_uint(As[(wm0 + 16*i + g + 8) * 68 + kb + q    ]);
            a[i][2] = __float_as_uint(As[(wm0 + 16*i + g    ) * 68 + kb + q + 4]);
            a[i][3] = __float_as_uint(As[(wm0 + 16*i + g + 8) * 68 + kb + q + 4]);
        }
        #pragma unroll
        for (int j = 0; j < 4; ++j) {
            b[j][0] = __float_as_uint(Bs[(wn0 + 8*j + g) * 68 + kb + q    ]);
            b[j][1] = __float_as_uint(Bs[(wn0 + 8*j + g) * 68 + kb + q + 4]);
        }
        #pragma unroll
        for (int i = 0; i < 4; ++i)
            #pragma unroll
            for (int j = 0; j < 4; ++j)
                MMA_TF32(acc[i][j], a[i], b[j]);
    }

    // Epilogue: write raw masked scores + per-row (m,s) partials.
    #pragma unroll
    for (int i = 0; i < 4; ++i) {
        #pragma unroll
        for (int rr = 0; rr < 2; ++rr) {
            const int R  = wm0 + 16*i + g + rr*8;   // row within block
            const int gr = row0 + R;
            float m_t = -INFINITY, s_t = 0.0f;
            float vals[8];
            #pragma unroll
            for (int j = 0; j < 4; ++j) {
                const int gc = col0 + wn0 + 8*j + 2*q;
                int2 mv = *(const int2*)&mask[(size_t)gr * SS + gc];
                float v0 = mv.x ? acc[i][j][rr*2 + 0] * 0.125f : -INFINITY;
                float v1 = mv.y ? acc[i][j][rr*2 + 1] * 0.125f : -INFINITY;
                *(float2*)&Cz[(size_t)gr * SS + gc] = make_float2(v0, v1);
                vals[j*2] = v0; vals[j*2+1] = v1;
                m_t = fmaxf(m_t, fmaxf(v0, v1));
            }
            #pragma unroll
            for (int e = 0; e < 8; ++e)
                s_t += (vals[e] > -INFINITY) ? __expf(vals[e] - m_t) : 0.0f;
            // reduce across q (4 lanes sharing this row)
            #pragma unroll
            for (int o = 1; o <= 2; o <<= 1) {
                float om = __shfl_xor_sync(0xffffffffu, m_t, o);
                float os = __shfl_xor_sync(0xffffffffu, s_t, o);
                sm_merge(m_t, s_t, om, os);
            }
            if (q == 0) {
                red_m[R * 4 + (wid & 3)] = m_t;
                red_s[R * 4 + (wid & 3)] = s_t;
            }
        }
    }
    __syncthreads();
    if (tid < 128) {
        float m = red_m[tid * 4], s = red_s[tid * 4];
        #pragma unroll
        for (int w = 1; w < 4; ++w)
            sm_merge(m, s, red_m[tid * 4 + w], red_s[tid * 4 + w]);
        Part[((size_t)z * SS + row0 + tid) * 16 + blockIdx.x] = make_float2(m, s);
    }
}

// ---------------------------------------------------------------------------
// Reduce partials -> per-row (max, 1/sum)
// ---------------------------------------------------------------------------
__global__ __launch_bounds__(256)
void reduce_stats(const float2* __restrict__ Part, float2* __restrict__ Stats)
{
    const int row = blockIdx.x * 256 + threadIdx.x;
    float2 p[16];
    #pragma unroll
    for (int i = 0; i < 16; ++i) p[i] = Part[(size_t)row * 16 + i];
    float M = -INFINITY;
    #pragma unroll
    for (int i = 0; i < 16; ++i) M = fmaxf(M, p[i].x);
    float S = 0.0f;
    #pragma unroll
    for (int i = 0; i < 16; ++i)
        S += (p[i].x > -INFINITY) ? p[i].y * __expf(p[i].x - M) : 0.0f;
    Stats[row] = make_float2(M, (S > 0.0f) ? 1.0f / S : 0.0f);
}

// ---------------------------------------------------------------------------
// AV fused with softmax-apply: reads raw scores, computes w=exp(x-M)*invS,
// writes normalized weights IN PLACE (final output; per-thread RMW of its
// own addresses -> race-free), and accumulates W@V.
// BM=128, BK=32, reg-staged double buffer, warp tile 32x32.
// FIX vs R3: Bs is [2][32][68] (V tile is 32x64; 36 was OOB into As).
// ---------------------------------------------------------------------------
__global__ __launch_bounds__(256, 2)
void mma_av(float* __restrict__ Wts, const float* __restrict__ Vh,
            const float2* __restrict__ Stats, float* __restrict__ Ctx)
{
    __shared__ float As[2][128][36];
    __shared__ float Bs[2][32][68];
    __shared__ float sM[128], sI[128];

    const int z = blockIdx.y;
    float* Aw = Wts + (size_t)z * SS * SS;
    const float* Vv = Vh + (size_t)z * SS * DH;
    const int row0 = blockIdx.x * 128;

    const int tid = threadIdx.x;
    const int wid = tid >> 5, lane = tid & 31;
    const int g = lane >> 2, q = lane & 3;
    const int wm0 = (wid >> 1) * 32;
    const int wn0 = (wid & 1) * 32;

    if (tid < 128) {
        float2 st = Stats[(size_t)z * SS + row0 + tid];
        sM[tid] = st.x; sI[tid] = st.y;
    }

    float acc[2][4][4];
    #pragma unroll
    for (int i = 0; i < 2; ++i)
        #pragma unroll
        for (int j = 0; j < 4; ++j)
            #pragma unroll
            for (int r = 0; r < 4; ++r) acc[i][j][r] = 0.0f;

    // prologue loads (tile 0)
    float4 ra[4], rb[2];
    #pragma unroll
    for (int it = 0; it < 4; ++it) {
        const int idx = tid + it * 256;
        const int r = idx >> 3, c4 = (idx & 7) << 2;
        ra[it] = *(const float4*)&Aw[(size_t)(row0 + r) * SS + c4];
    }
    #pragma unroll
    for (int it = 0; it < 2; ++it) {
        const int idx = tid + it * 256;
        const int r = idx >> 4, c4 = (idx & 15) << 2;
        rb[it] = *(const float4*)&Vv[(size_t)r * DH + c4];
    }
    __syncthreads();   // stats visible

    for (int t = 0; t < SS / 32; ++t) {
        const int kt = t * 32;
        const int st = t & 1;
        // transform + store tile t (regs -> smem, normalized weights -> gmem)
        #pragma unroll
        for (int it = 0; it < 4; ++it) {
            const int idx = tid + it * 256;
            const int r = idx >> 3, c4 = (idx & 7) << 2;
            const float M = sM[r], I = sI[r];
            float4 w;
            w.x = __expf(ra[it].x - M) * I;
            w.y = __expf(ra[it].y - M) * I;
            w.z = __expf(ra[it].z - M) * I;
            w.w = __expf(ra[it].w - M) * I;
            *(float4*)&Aw[(size_t)(row0 + r) * SS + kt + c4] = w;   // final weights
            *(float4*)&As[st][r][c4] = make_float4(to_tf32(w.x), to_tf32(w.y),
                                                   to_tf32(w.z), to_tf32(w.w));
        }
        #pragma unroll
        for (int it = 0; it < 2; ++it) {
            const int idx = tid + it * 256;
            const int r = idx >> 4, c4 = (idx & 15) << 2;
            *(float4*)&Bs[st][r][c4] = make_float4(to_tf32(rb[it].x), to_tf32(rb[it].y),
                                                   to_tf32(rb[it].z), to_tf32(rb[it].w));
        }
        __syncthreads();
        // prefetch tile t+1 into regs (overlaps with MMA below)
        if (t + 1 < SS / 32) {
            const int kt2 = kt + 32;
            #pragma unroll
            for (int it = 0; it < 4; ++it) {
                const int idx = tid + it * 256;
                const int r = idx >> 3, c4 = (idx & 7) << 2;
                ra[it] = *(const float4*)&Aw[(size_t)(row0 + r) * SS + kt2 + c4];
            }
            #pragma unroll
            for (int it = 0; it < 2; ++it) {
                const int idx = tid + it * 256;
                const int r = idx >> 4, c4 = (idx & 15) << 2;
                rb[it] = *(const float4*)&Vv[(size_t)(kt2 + r) * DH + c4];
            }
        }
        #pragma unroll
        for (int kk = 0; kk < 4; ++kk) {
            const int kb = kk * 8;
            uint32_t a[2][4], b[4][2];
            #pragma unroll
            for (int i = 0; i < 2; ++i) {
                a[i][0] = __float_as_uint(As[st][wm0 + 16*i + g    ][kb + q    ]);
                a[i][1] = __float_as_uint(As[st][wm0 + 16*i + g + 8][kb + q    ]);
                a[i][2] = __float_as_uint(As[st][wm0 + 16*i + g    ][kb + q + 4]);
                a[i][3] = __float_as_uint(As[st][wm0 + 16*i + g + 8][kb + q + 4]);
            }
            #pragma unroll
            for (int j = 0; j < 4; ++j) {
                b[j][0] = __float_as_uint(Bs[st][kb + q    ][wn0 + 8*j + g]);
                b[j][1] = __float_as_uint(Bs[st][kb + q + 4][wn0 + 8*j + g]);
            }
            #pragma unroll
            for (int i = 0; i < 2; ++i)
                #pragma unroll
                for (int j = 0; j < 4; ++j)
                    MMA_TF32(acc[i][j], a[i], b[j]);
        }
    }

    const int b = z / HH, h = z % HH;
    #pragma unroll
    for (int i = 0; i < 2; ++i) {
        #pragma unroll
        for (int rr = 0; rr < 2; ++rr) {
            const int s = row0 + wm0 + 16*i + g + rr*8;
            #pragma unroll
            for (int j = 0; j < 4; ++j) {
                const int n = wn0 + 8*j + 2*q;
                *(float2*)&Ctx[((size_t)(b*SS + s))*DD + h*64 + n] =
                    make_float2(acc[i][j][rr*2], acc[i][j][rr*2 + 1]);
            }
        }
    }
}

// ---------------------------------------------------------------------------
extern "C" void kernel_launch(void* const* d_in, const int* in_sizes, int n_in,
                              void* d_out, int out_size)
{
    const float* q       = (const float*)d_in[0];
    const float* k       = (const float*)d_in[1];
    const float* v       = (const float*)d_in[2];
    const int*   mask    = (const int*)d_in[3];
    const float* wq_w    = (const float*)d_in[4];
    const float* wq_b    = (const float*)d_in[5];
    const float* wk_w    = (const float*)d_in[6];
    const float* wk_b    = (const float*)d_in[7];
    const float* wv_w    = (const float*)d_in[8];
    const float* wv_b    = (const float*)d_in[9];
    const float* dense_w = (const float*)d_in[10];
    const float* dense_b = (const float*)d_in[11];

    float* out = (float*)d_out;
    float* wts = out + (size_t)BB * SS * DD;

    void *pQ, *pK, *pV, *pC, *pP, *pS;
    cudaGetSymbolAddress(&pQ, g_Q);
    cudaGetSymbolAddress(&pK, g_K);
    cudaGetSymbolAddress(&pV, g_V);
    cudaGetSymbolAddress(&pC, g_Ctx);
    cudaGetSymbolAddress(&pP, g_Part);
    cudaGetSymbolAddress(&pS, g_Stats);
    float*  gQ = (float*)pQ;
    float*  gK = (float*)pK;
    float*  gV = (float*)pV;
    float*  gC = (float*)pC;
    float2* gP = (float2*)pP;
    float2* gS = (float2*)pS;

    const int SM_GEMM = 73728;   // mma_nt dynamic smem
    const int SM_SC   = 73728;   // scores dynamic smem
    static int inited = 0;
    if (!inited) {
        cudaFuncSetAttribute(mma_nt<0>, cudaFuncAttributeMaxDynamicSharedMemorySize, SM_GEMM);
        cudaFuncSetAttribute(mma_nt<1>, cudaFuncAttributeMaxDynamicSharedMemorySize, SM_GEMM);
        cudaFuncSetAttribute(scores_kernel, cudaFuncAttributeMaxDynamicSharedMemorySize, SM_SC);
        inited = 1;
    }

    const dim3 blk(256);
    const dim3 gproj(DD / 128, MROWS / 128, 1);       // (8, 32)

    mma_nt<0><<<gproj, blk, SM_GEMM>>>(q, wq_w, wq_b, gQ);
    mma_nt<0><<<gproj, blk, SM_GEMM>>>(k, wk_w, wk_b, gK);
    mma_nt<0><<<gproj, blk, SM_GEMM>>>(v, wv_w, wv_b, gV);

    const dim3 gsc(SS / 128, SS / 128, BH);           // (16, 16, 32)
    scores_kernel<<<gsc, blk, SM_SC>>>(gQ, gK, mask, wts, gP);

    reduce_stats<<<NROWTOT / 256, 256>>>(gP, gS);

    const dim3 gav(SS / 128, BH, 1);                  // (16, 32)
    mma_av<<<gav, blk>>>(wts, gV, gS, gC);

    mma_nt<1><<<gproj, blk, SM_GEMM>>>(gC, dense_w, dense_b, out);
}